// round 1
// baseline (speedup 1.0000x reference)
#include <cuda_runtime.h>
#include <math.h>

// Problem constants
#define Bsz 2
#define Nn  1024
#define Dd  512
#define Hh  16
#define DHd 32
#define QKV_OUT 1536

// Scratch (device globals; no allocation allowed)
__device__ float g_q[Bsz*Hh*Nn*DHd];     // [B,H,N,DH]
__device__ float g_k[Bsz*Hh*Nn*DHd];     // [B,H,N,DH]
__device__ float g_v[Bsz*Hh*Nn*DHd];     // [B,H,N,DH]
__device__ float g_att[Bsz*Nn*Dd];       // [B,N,H*DH] attention output
__device__ float g_y[Bsz*Nn*Dd];         // pre-LN residual

// ---------------------------------------------------------------------------
// Kernel 1: QKV projection GEMM.  C[m,o] = sum_k x[m,k]*att_w[o,k]
// M=2048, O=1536, K=512. 64x64 tiles, 256 threads, 4x4 microtile.
// Epilogue scatters into g_q/g_k/g_v with [B,H,N,DH] layout.
// ---------------------------------------------------------------------------
__global__ __launch_bounds__(256) void gemm_qkv_kernel(
    const float* __restrict__ x, const float* __restrict__ w)
{
    __shared__ float As[16][68];
    __shared__ float Ws[16][68];
    const int tid = threadIdx.x;
    const int m0 = blockIdx.y * 64;
    const int o0 = blockIdx.x * 64;
    const int tx = tid & 15, ty = tid >> 4;
    const int lr = tid >> 2;            // 0..63
    const int lk = (tid & 3) << 2;      // 0,4,8,12

    float acc[4][4] = {};

    for (int k0 = 0; k0 < 512; k0 += 16) {
        float4 a  = *(const float4*)&x[(m0 + lr)*512 + k0 + lk];
        float4 bq = *(const float4*)&w[(o0 + lr)*512 + k0 + lk];
        As[lk+0][lr]=a.x;  As[lk+1][lr]=a.y;  As[lk+2][lr]=a.z;  As[lk+3][lr]=a.w;
        Ws[lk+0][lr]=bq.x; Ws[lk+1][lr]=bq.y; Ws[lk+2][lr]=bq.z; Ws[lk+3][lr]=bq.w;
        __syncthreads();
        #pragma unroll
        for (int kk = 0; kk < 16; kk++) {
            float4 av = *(const float4*)&As[kk][ty*4];
            float4 wv = *(const float4*)&Ws[kk][tx*4];
            float aa[4] = {av.x,av.y,av.z,av.w};
            float ww[4] = {wv.x,wv.y,wv.z,wv.w};
            #pragma unroll
            for (int i=0;i<4;i++)
                #pragma unroll
                for (int j=0;j<4;j++)
                    acc[i][j] += aa[i]*ww[j];
        }
        __syncthreads();
    }

    #pragma unroll
    for (int i=0;i<4;i++) {
        int m  = m0 + ty*4 + i;
        int bb = m >> 10, ir = m & 1023;
        #pragma unroll
        for (int j=0;j<4;j++) {
            int o = o0 + tx*4 + j;
            int which = o >> 9;
            int h = (o & 511) >> 5;
            int d = o & 31;
            float* dst = (which == 0) ? g_q : ((which == 1) ? g_k : g_v);
            dst[(((bb*Hh + h)*Nn) + ir)*DHd + d] = acc[i][j];
        }
    }
}

// ---------------------------------------------------------------------------
// Kernel 2: Fused attention (flash-style).
// Block = (qblock of 64 queries, head, batch); 64 threads; thread owns 1 query.
// Scores computed on the fly with all additive biases; online softmax;
// accumulates prob@V; writes att_vec [B,N,H*DH].
// ---------------------------------------------------------------------------
__global__ __launch_bounds__(64) void attn_kernel(
    const float* __restrict__ pdist, const float* __restrict__ angle,
    const float* __restrict__ adj,   const unsigned char* __restrict__ mask,
    const float* __restrict__ gamma_p, const float* __restrict__ gamma_adj,
    const float* __restrict__ w_bias)
{
    const int b  = blockIdx.z;
    const int h  = blockIdx.y;
    const int i0 = blockIdx.x * 64;
    const int t  = threadIdx.x;
    const int i  = i0 + t;

    __shared__ float sK[16][32];
    __shared__ float sV[16][32];

    // Load query row, pre-scaled by 1/sqrt(DH)
    float q[32];
    {
        const float4* q4 = (const float4*)&g_q[(((b*Hh + h)*Nn) + i)*DHd];
        #pragma unroll
        for (int c = 0; c < 8; c++) {
            float4 v = q4[c];
            q[c*4+0] = v.x * 0.17677669529663689f;
            q[c*4+1] = v.y * 0.17677669529663689f;
            q[c*4+2] = v.z * 0.17677669529663689f;
            q[c*4+3] = v.w * 0.17677669529663689f;
        }
    }
    const float gp  = gamma_p[h];
    const float ga  = gamma_adj[h];
    const float wb0 = w_bias[h*2+0];
    const float wb1 = w_bias[h*2+1];

    const float* Kb = &g_k[((b*Hh + h)*Nn)*DHd];
    const float* Vb = &g_v[((b*Hh + h)*Nn)*DHd];
    const float* pd = &pdist[(b*Nn + i)*Nn];
    const float* aj = &adj  [(b*Nn + i)*Nn];
    const float* an = &angle[((size_t)(b*Nn + i)*Nn)*2];
    const unsigned char* mk = &mask[b*Nn];

    float m = -INFINITY, l = 0.f;
    float acc[32] = {};

    for (int j0 = 0; j0 < Nn; j0 += 16) {
        __syncthreads();
        // Cooperative K/V tile load: 512 floats each, 64 threads -> 2 float4 each
        {
            float4* dK = (float4*)&sK[0][0];
            float4* dV = (float4*)&sV[0][0];
            const float4* sKg = (const float4*)(Kb + j0*DHd);
            const float4* sVg = (const float4*)(Vb + j0*DHd);
            dK[t]      = sKg[t];
            dK[t + 64] = sKg[t + 64];
            dV[t]      = sVg[t];
            dV[t + 64] = sVg[t + 64];
        }
        __syncthreads();

        float s[16];
        #pragma unroll
        for (int jj = 0; jj < 16; jj++) {
            const float4* k4 = (const float4*)sK[jj];
            float acc_s = 0.f;
            #pragma unroll
            for (int c = 0; c < 8; c++) {
                float4 kv = k4[c];
                acc_s += q[c*4+0]*kv.x + q[c*4+1]*kv.y
                       + q[c*4+2]*kv.z + q[c*4+3]*kv.w;
            }
            const int j = j0 + jj;
            float2 a2 = *(const float2*)&an[2*(size_t)j];
            acc_s = acc_s - gp*pd[j] + wb0*a2.x + wb1*a2.y + ga*aj[j];
            if (mk[j]) acc_s = -1e9f;
            s[jj] = acc_s;
        }

        float tmax = s[0];
        #pragma unroll
        for (int jj = 1; jj < 16; jj++) tmax = fmaxf(tmax, s[jj]);
        float mnew = fmaxf(m, tmax);
        float corr = __expf(m - mnew);
        m = mnew;
        l *= corr;
        #pragma unroll
        for (int d = 0; d < 32; d++) acc[d] *= corr;

        #pragma unroll
        for (int jj = 0; jj < 16; jj++) {
            float p = __expf(s[jj] - m);
            l += p;
            const float4* v4 = (const float4*)sV[jj];
            #pragma unroll
            for (int c = 0; c < 8; c++) {
                float4 vv = v4[c];
                acc[c*4+0] += p * vv.x;
                acc[c*4+1] += p * vv.y;
                acc[c*4+2] += p * vv.z;
                acc[c*4+3] += p * vv.w;
            }
        }
    }

    const float inv = 1.0f / l;
    float4* out4 = (float4*)&g_att[((size_t)(b*Nn + i))*Dd + h*DHd];
    #pragma unroll
    for (int c = 0; c < 8; c++) {
        float4 o;
        o.x = acc[c*4+0]*inv; o.y = acc[c*4+1]*inv;
        o.z = acc[c*4+2]*inv; o.w = acc[c*4+3]*inv;
        out4[c] = o;
    }
}

// ---------------------------------------------------------------------------
// Kernel 3: FF GEMM with fused residual.  y[m,o] = x[m,o] + ff_b[o]
//           + sum_k att[m,k]*ff_w[o,k].   M=2048, O=512, K=512.
// ---------------------------------------------------------------------------
__global__ __launch_bounds__(256) void gemm_ff_kernel(
    const float* __restrict__ ffw, const float* __restrict__ x,
    const float* __restrict__ ffb)
{
    __shared__ float As[16][68];
    __shared__ float Ws[16][68];
    const int tid = threadIdx.x;
    const int m0 = blockIdx.y * 64;
    const int o0 = blockIdx.x * 64;
    const int tx = tid & 15, ty = tid >> 4;
    const int lr = tid >> 2;
    const int lk = (tid & 3) << 2;

    float acc[4][4] = {};

    for (int k0 = 0; k0 < 512; k0 += 16) {
        float4 a  = *(const float4*)&g_att[(m0 + lr)*512 + k0 + lk];
        float4 bq = *(const float4*)&ffw[(o0 + lr)*512 + k0 + lk];
        As[lk+0][lr]=a.x;  As[lk+1][lr]=a.y;  As[lk+2][lr]=a.z;  As[lk+3][lr]=a.w;
        Ws[lk+0][lr]=bq.x; Ws[lk+1][lr]=bq.y; Ws[lk+2][lr]=bq.z; Ws[lk+3][lr]=bq.w;
        __syncthreads();
        #pragma unroll
        for (int kk = 0; kk < 16; kk++) {
            float4 av = *(const float4*)&As[kk][ty*4];
            float4 wv = *(const float4*)&Ws[kk][tx*4];
            float aa[4] = {av.x,av.y,av.z,av.w};
            float ww[4] = {wv.x,wv.y,wv.z,wv.w};
            #pragma unroll
            for (int i=0;i<4;i++)
                #pragma unroll
                for (int j=0;j<4;j++)
                    acc[i][j] += aa[i]*ww[j];
        }
        __syncthreads();
    }

    #pragma unroll
    for (int i=0;i<4;i++) {
        int m = m0 + ty*4 + i;
        #pragma unroll
        for (int j=0;j<4;j++) {
            int o = o0 + tx*4 + j;
            g_y[m*512 + o] = acc[i][j] + x[m*512 + o] + ffb[o];
        }
    }
}

// ---------------------------------------------------------------------------
// Kernel 4: LayerNorm over rows of g_y -> out.  128 threads/row, float4 each.
// ---------------------------------------------------------------------------
__global__ __launch_bounds__(128) void ln_kernel(
    const float* __restrict__ lnw, const float* __restrict__ lnb,
    float* __restrict__ out)
{
    const int row = blockIdx.x;
    const int t = threadIdx.x;
    const float4 v = ((const float4*)&g_y[(size_t)row*512])[t];

    float s  = v.x + v.y + v.z + v.w;
    float ss = v.x*v.x + v.y*v.y + v.z*v.z + v.w*v.w;

    __shared__ float rs[4], rss[4];
    #pragma unroll
    for (int off = 16; off > 0; off >>= 1) {
        s  += __shfl_down_sync(0xffffffffu, s,  off);
        ss += __shfl_down_sync(0xffffffffu, ss, off);
    }
    if ((t & 31) == 0) { rs[t >> 5] = s; rss[t >> 5] = ss; }
    __syncthreads();
    float sum  = rs[0]  + rs[1]  + rs[2]  + rs[3];
    float sums = rss[0] + rss[1] + rss[2] + rss[3];

    const float mu  = sum * (1.0f/512.0f);
    const float var = sums * (1.0f/512.0f) - mu*mu;
    const float rstd = rsqrtf(var + 1e-5f);

    const float4 w = ((const float4*)lnw)[t];
    const float4 b = ((const float4*)lnb)[t];
    float4 o;
    o.x = (v.x - mu)*rstd*w.x + b.x;
    o.y = (v.y - mu)*rstd*w.y + b.y;
    o.z = (v.z - mu)*rstd*w.z + b.z;
    o.w = (v.w - mu)*rstd*w.w + b.w;
    ((float4*)&out[(size_t)row*512])[t] = o;
}

// ---------------------------------------------------------------------------
// Launch.  Input order (metadata): x, pdist, angle, adj, mask, gamma_p,
// gamma_adj, w_bias, att_w, ff_w, ff_b, ln_w, ln_b.
// ---------------------------------------------------------------------------
extern "C" void kernel_launch(void* const* d_in, const int* in_sizes, int n_in,
                              void* d_out, int out_size)
{
    const float* x        = (const float*)d_in[0];
    const float* pdist    = (const float*)d_in[1];
    const float* angle    = (const float*)d_in[2];
    const float* adj      = (const float*)d_in[3];
    const unsigned char* mask = (const unsigned char*)d_in[4];
    const float* gamma_p  = (const float*)d_in[5];
    const float* gamma_adj= (const float*)d_in[6];
    const float* w_bias   = (const float*)d_in[7];
    const float* att_w    = (const float*)d_in[8];
    const float* ff_w     = (const float*)d_in[9];
    const float* ff_b     = (const float*)d_in[10];
    const float* ln_w     = (const float*)d_in[11];
    const float* ln_b     = (const float*)d_in[12];
    float* out = (float*)d_out;

    // 1. QKV projection: grid (O/64, M/64) = (24, 32)
    gemm_qkv_kernel<<<dim3(QKV_OUT/64, (Bsz*Nn)/64), 256>>>(x, att_w);
    // 2. Fused attention: grid (N/64, H, B), 64 threads
    attn_kernel<<<dim3(Nn/64, Hh, Bsz), 64>>>(pdist, angle, adj, mask,
                                              gamma_p, gamma_adj, w_bias);
    // 3. FF GEMM + residual: grid (512/64, 2048/64) = (8, 32)
    gemm_ff_kernel<<<dim3(Dd/64, (Bsz*Nn)/64), 256>>>(ff_w, x, ff_b);
    // 4. LayerNorm: one block per row
    ln_kernel<<<Bsz*Nn, 128>>>(ln_w, ln_b, out);
}